// round 1
// baseline (speedup 1.0000x reference)
#include <cuda_runtime.h>

#define MAX_N 50000
#define HDIM  64

// ---------------- scratch (no allocations allowed) ----------------
__device__ float g_tx0[MAX_N * HDIM];
__device__ float g_tx1[MAX_N * HDIM];
__device__ float g_bufA[MAX_N * HDIM];
__device__ float g_bufB[MAX_N * HDIM];
__device__ float g_e0[MAX_N * 2];
__device__ float g_e1[MAX_N * 2];
__device__ unsigned int g_min_key;

// monotone float<->uint encoding so atomicMin(uint) == float min
__device__ __forceinline__ unsigned fenc(float f) {
    unsigned b = __float_as_uint(f);
    return (b & 0x80000000u) ? ~b : (b | 0x80000000u);
}
__device__ __forceinline__ float fdec(unsigned k) {
    unsigned b = (k & 0x80000000u) ? (k ^ 0x80000000u) : ~k;
    return __uint_as_float(b);
}

// ---------------- fused triple GEMM: {C0,C1,Cl} = relu?(A) @ {W0,W1,Wl}(+bias) ----------------
// A: [M,K] row-major, weights [K,64] row-major, outputs [M,64].
// blockIdx.y selects which weight matrix this CTA computes.
template<bool RELU_IN>
__global__ void __launch_bounds__(256) gemm3_kernel(
    const float* __restrict__ A, int M, int K,
    const float* __restrict__ W0, const float* __restrict__ W1,
    const float* __restrict__ Wl, const float* __restrict__ bias,
    float* __restrict__ C0, float* __restrict__ C1, float* __restrict__ Cl)
{
    constexpr int BM = 128, BN = 64, BK = 32;
    __shared__ float As[BK][BM];   // transposed A tile
    __shared__ float Bs[BK][BN];

    const float* W;
    float* C;
    bool use_bias = false;
    if      (blockIdx.y == 0) { W = W0; C = C0; }
    else if (blockIdx.y == 1) { W = W1; C = C1; }
    else                      { W = Wl; C = Cl; use_bias = true; }

    const int tid = threadIdx.x;
    const int tn = tid & 15;    // col group (4 cols)
    const int tm = tid >> 4;    // row group (8 rows)
    const int rowBase = blockIdx.x * BM;

    float acc[8][4];
    #pragma unroll
    for (int i = 0; i < 8; i++)
        #pragma unroll
        for (int j = 0; j < 4; j++) acc[i][j] = 0.f;

    for (int k0 = 0; k0 < K; k0 += BK) {
        // stage A tile (transposed); 1024 float4s over 256 threads
        #pragma unroll
        for (int it = 0; it < 4; it++) {
            int f4 = tid + it * 256;
            int r  = f4 >> 3;              // 0..127
            int kq = (f4 & 7) << 2;        // 0,4,...,28
            float4 v = make_float4(0.f, 0.f, 0.f, 0.f);
            int grow = rowBase + r;
            if (grow < M) {
                v = *(const float4*)&A[(long)grow * K + k0 + kq];
                if (RELU_IN) {
                    v.x = fmaxf(v.x, 0.f); v.y = fmaxf(v.y, 0.f);
                    v.z = fmaxf(v.z, 0.f); v.w = fmaxf(v.w, 0.f);
                }
            }
            As[kq + 0][r] = v.x; As[kq + 1][r] = v.y;
            As[kq + 2][r] = v.z; As[kq + 3][r] = v.w;
        }
        // stage W tile
        #pragma unroll
        for (int it = 0; it < 2; it++) {
            int f4 = tid + it * 256;
            int kk = f4 >> 4;
            int nq = (f4 & 15) << 2;
            *(float4*)&Bs[kk][nq] = *(const float4*)&W[(long)(k0 + kk) * BN + nq];
        }
        __syncthreads();

        #pragma unroll
        for (int kk = 0; kk < BK; kk++) {
            float4 a0 = *(const float4*)&As[kk][tm * 8];
            float4 a1 = *(const float4*)&As[kk][tm * 8 + 4];
            float4 b  = *(const float4*)&Bs[kk][tn * 4];
            float av[8] = {a0.x, a0.y, a0.z, a0.w, a1.x, a1.y, a1.z, a1.w};
            float bv[4] = {b.x, b.y, b.z, b.w};
            #pragma unroll
            for (int i = 0; i < 8; i++)
                #pragma unroll
                for (int j = 0; j < 4; j++)
                    acc[i][j] = fmaf(av[i], bv[j], acc[i][j]);
        }
        __syncthreads();
    }

    float4 bb = make_float4(0.f, 0.f, 0.f, 0.f);
    if (use_bias) bb = *(const float4*)&bias[tn * 4];
    #pragma unroll
    for (int i = 0; i < 8; i++) {
        int grow = rowBase + tm * 8 + i;
        if (grow < M) {
            float4 o;
            o.x = acc[i][0] + bb.x; o.y = acc[i][1] + bb.y;
            o.z = acc[i][2] + bb.z; o.w = acc[i][3] + bb.w;
            *(float4*)&C[(long)grow * BN + tn * 4] = o;
        }
    }
}

// ---------------- edge scatter: agg[dst] += tx[etype][src], 64 floats ----------------
// 16 threads per edge, one float4 + one red.v4 each.
__global__ void scatter64_kernel(
    const float* __restrict__ t0, const float* __restrict__ t1,
    const int* __restrict__ src, const int* __restrict__ dst,
    const int* __restrict__ et, float* __restrict__ agg, int E)
{
    long idx = (long)blockIdx.x * blockDim.x + threadIdx.x;
    int e = (int)(idx >> 4);
    if (e >= E) return;
    int q = ((int)idx & 15) << 2;
    int s = src[e], d = dst[e];
    const float* t = et[e] ? t1 : t0;
    float4 v = *(const float4*)&t[(long)s * 64 + q];
    float* p = &agg[(long)d * 64 + q];
    asm volatile("red.global.add.v4.f32 [%0], {%1,%2,%3,%4};"
                 :: "l"(p), "f"(v.x), "f"(v.y), "f"(v.z), "f"(v.w) : "memory");
}

// ---------------- layer 3: per-node tiny GEMMs (64 -> 2 per matrix) ----------------
__global__ void layer3_kernel(
    const float* __restrict__ H,
    const float* __restrict__ W3, const float* __restrict__ L3,
    const float* __restrict__ b3,
    float* __restrict__ e0, float* __restrict__ e1,
    float* __restrict__ out, int N)
{
    __shared__ float sW0[128], sW1[128], sL[128], sb[2];
    int tid = threadIdx.x;
    for (int i = tid; i < 128; i += blockDim.x) {
        sW0[i] = W3[i];
        sW1[i] = W3[128 + i];
        sL[i]  = L3[i];
    }
    if (tid < 2) sb[tid] = b3[tid];
    __syncthreads();

    int n = blockIdx.x * blockDim.x + tid;
    if (n >= N) return;
    const float* h = &H[(long)n * 64];
    float a0 = 0.f, a1 = 0.f, c0 = 0.f, c1 = 0.f, l0 = 0.f, l1 = 0.f;
    #pragma unroll
    for (int k = 0; k < 64; k += 4) {
        float4 hv = *(const float4*)&h[k];
        float xv[4] = {fmaxf(hv.x, 0.f), fmaxf(hv.y, 0.f),
                       fmaxf(hv.z, 0.f), fmaxf(hv.w, 0.f)};
        #pragma unroll
        for (int j = 0; j < 4; j++) {
            int kk = k + j;
            a0 = fmaf(xv[j], sW0[kk * 2 + 0], a0);
            a1 = fmaf(xv[j], sW0[kk * 2 + 1], a1);
            c0 = fmaf(xv[j], sW1[kk * 2 + 0], c0);
            c1 = fmaf(xv[j], sW1[kk * 2 + 1], c1);
            l0 = fmaf(xv[j], sL[kk * 2 + 0], l0);
            l1 = fmaf(xv[j], sL[kk * 2 + 1], l1);
        }
    }
    *(float2*)&e0[n * 2] = make_float2(a0, a1);
    *(float2*)&e1[n * 2] = make_float2(c0, c1);
    *(float2*)&out[n * 2] = make_float2(l0 + sb[0], l1 + sb[1]);
}

// ---------------- edge scatter for layer 3 (2 floats/edge) ----------------
__global__ void scatter2_kernel(
    const float* __restrict__ e0v, const float* __restrict__ e1v,
    const int* __restrict__ src, const int* __restrict__ dst,
    const int* __restrict__ et, float* __restrict__ out, int E)
{
    int e = blockIdx.x * blockDim.x + threadIdx.x;
    if (e >= E) return;
    const float* t = et[e] ? e1v : e0v;
    float2 v = *(const float2*)&t[(long)src[e] * 2];
    float* p = &out[(long)dst[e] * 2];
    asm volatile("red.global.add.v2.f32 [%0], {%1,%2};"
                 :: "l"(p), "f"(v.x), "f"(v.y) : "memory");
}

// ---------------- global min + mask ----------------
__global__ void init_min_kernel() { g_min_key = 0xFFFFFFFFu; }

__global__ void min_kernel(const float* __restrict__ v, int n)
{
    float m = 3.402823466e+38f;
    for (int i = blockIdx.x * blockDim.x + threadIdx.x; i < n;
         i += gridDim.x * blockDim.x)
        m = fminf(m, v[i]);
    #pragma unroll
    for (int o = 16; o; o >>= 1)
        m = fminf(m, __shfl_xor_sync(0xffffffffu, m, o));
    __shared__ float sm[8];
    if ((threadIdx.x & 31) == 0) sm[threadIdx.x >> 5] = m;
    __syncthreads();
    if (threadIdx.x < 8) {
        m = sm[threadIdx.x];
        #pragma unroll
        for (int o = 4; o; o >>= 1)
            m = fminf(m, __shfl_xor_sync(0xffu, m, o));
        if (threadIdx.x == 0) atomicMin(&g_min_key, fenc(m));
    }
}

__global__ void mask_kernel(float* __restrict__ out,
                            const int* __restrict__ cs,
                            const int* __restrict__ ms, int N)
{
    int n = blockIdx.x * blockDim.x + threadIdx.x;
    if (n >= N) return;
    float mn = fdec(g_min_key) - 1.0f;
    float2 v = *(float2*)&out[n * 2];
    if (cs[n] >= ms[n] - 1) v.x = mn;
    if (cs[n] == 0)         v.y = mn;
    *(float2*)&out[n * 2] = v;
}

// ---------------- launch ----------------
extern "C" void kernel_launch(void* const* d_in, const int* in_sizes, int n_in,
                              void* d_out, int out_size)
{
    const float* x  = (const float*)d_in[0];
    const int* src  = (const int*)d_in[1];
    const int* dst  = (const int*)d_in[2];
    const int* et   = (const int*)d_in[3];
    const int* cs   = (const int*)d_in[4];
    const int* ms   = (const int*)d_in[5];
    const float* W1 = (const float*)d_in[6];
    const float* L1 = (const float*)d_in[7];
    const float* b1 = (const float*)d_in[8];
    const float* W2 = (const float*)d_in[9];
    const float* L2 = (const float*)d_in[10];
    const float* b2 = (const float*)d_in[11];
    const float* W3 = (const float*)d_in[12];
    const float* L3 = (const float*)d_in[13];
    const float* b3 = (const float*)d_in[14];

    const int N = in_sizes[0] / 128;
    const int E = in_sizes[1];
    float* out = (float*)d_out;

    float *tx0, *tx1, *bufA, *bufB, *e0, *e1;
    cudaGetSymbolAddress((void**)&tx0,  g_tx0);
    cudaGetSymbolAddress((void**)&tx1,  g_tx1);
    cudaGetSymbolAddress((void**)&bufA, g_bufA);
    cudaGetSymbolAddress((void**)&bufB, g_bufB);
    cudaGetSymbolAddress((void**)&e0,   g_e0);
    cudaGetSymbolAddress((void**)&e1,   g_e1);

    dim3 gemm_grid((N + 127) / 128, 3);
    int scat_blocks = (E * 16 + 255) / 256;

    // layer 1: x[N,128] -> tx0/tx1/bufA[N,64]; then scatter into bufA
    gemm3_kernel<false><<<gemm_grid, 256>>>(x, N, 128,
        W1, W1 + 128 * 64, L1, b1, tx0, tx1, bufA);
    scatter64_kernel<<<scat_blocks, 256>>>(tx0, tx1, src, dst, et, bufA, E);

    // layer 2: relu(bufA)[N,64] -> tx0/tx1/bufB; then scatter into bufB
    gemm3_kernel<true><<<gemm_grid, 256>>>(bufA, N, 64,
        W2, W2 + 64 * 64, L2, b2, tx0, tx1, bufB);
    scatter64_kernel<<<scat_blocks, 256>>>(tx0, tx1, src, dst, et, bufB, E);

    // layer 3: relu(bufB) -> per-edge 2-float messages + self-loop into out
    layer3_kernel<<<(N + 255) / 256, 256>>>(bufB, W3, L3, b3, e0, e1, out, N);
    scatter2_kernel<<<(E + 255) / 256, 256>>>(e0, e1, src, dst, et, out, E);

    // global min then action mask
    init_min_kernel<<<1, 1>>>();
    min_kernel<<<160, 256>>>(out, N * 2);
    mask_kernel<<<(N + 255) / 256, 256>>>(out, cs, ms, N);
}